// round 3
// baseline (speedup 1.0000x reference)
#include <cuda_runtime.h>
#include <math.h>

#define EDIM 1024
#define TLEN 1024
#define BATCH 4
#define NHEAD 16
#define HDIM 64
#define MROWS (BATCH * TLEN)   // 4096

// ---------------- scratch (device globals: no runtime allocation) ----------
__device__ float g_q[(size_t)MROWS * EDIM];    // Q proj, later reused as out-proj result
__device__ float g_k[(size_t)MROWS * EDIM];
__device__ float g_v[(size_t)MROWS * EDIM];
__device__ float g_att[(size_t)MROWS * EDIM];  // merged attention output (B,T,E)

// ============================================================================
// GEMM: C[M,N] = A[M,K] @ W[N,K]^T + bias   (both row-major, K contiguous)
// BM=BN=128, BK=16, 256 threads, 8x8 micro-tile per thread.
// ============================================================================
__global__ __launch_bounds__(256) void gemm_nt_bias(
    const float* __restrict__ A, const float* __restrict__ W,
    const float* __restrict__ bias, float* __restrict__ C,
    int N, int K)
{
    __shared__ float As[16][132];
    __shared__ float Ws[16][132];

    const int t  = threadIdx.x;
    const int tx = t & 15;        // n-block
    const int ty = t >> 4;        // m-block
    const int n0 = blockIdx.x * 128;
    const int m0 = blockIdx.y * 128;

    float acc[8][8];
#pragma unroll
    for (int i = 0; i < 8; i++)
#pragma unroll
        for (int j = 0; j < 8; j++) acc[i][j] = 0.0f;

    for (int k0 = 0; k0 < K; k0 += 16) {
        // Load A tile (128x16) and W tile (128x16), transposed into [k][row]
#pragma unroll
        for (int p = 0; p < 2; p++) {
            int id  = t + p * 256;          // 0..511
            int row = id >> 2;              // 0..127
            int kq  = id & 3;               // which float4 along K
            float4 av = *(const float4*)&A[(m0 + row) * K + k0 + kq * 4];
            As[kq * 4 + 0][row] = av.x;
            As[kq * 4 + 1][row] = av.y;
            As[kq * 4 + 2][row] = av.z;
            As[kq * 4 + 3][row] = av.w;
            float4 wv = *(const float4*)&W[(n0 + row) * K + k0 + kq * 4];
            Ws[kq * 4 + 0][row] = wv.x;
            Ws[kq * 4 + 1][row] = wv.y;
            Ws[kq * 4 + 2][row] = wv.z;
            Ws[kq * 4 + 3][row] = wv.w;
        }
        __syncthreads();

#pragma unroll
        for (int k = 0; k < 16; k++) {
            float a[8], w[8];
            *(float4*)&a[0] = *(const float4*)&As[k][ty * 8];
            *(float4*)&a[4] = *(const float4*)&As[k][ty * 8 + 4];
            *(float4*)&w[0] = *(const float4*)&Ws[k][tx * 8];
            *(float4*)&w[4] = *(const float4*)&Ws[k][tx * 8 + 4];
#pragma unroll
            for (int i = 0; i < 8; i++)
#pragma unroll
                for (int j = 0; j < 8; j++)
                    acc[i][j] = fmaf(a[i], w[j], acc[i][j]);
        }
        __syncthreads();
    }

    float bb[8];
    *(float4*)&bb[0] = *(const float4*)&bias[n0 + tx * 8];
    *(float4*)&bb[4] = *(const float4*)&bias[n0 + tx * 8 + 4];

#pragma unroll
    for (int i = 0; i < 8; i++) {
        float4 o0, o1;
        o0.x = acc[i][0] + bb[0]; o0.y = acc[i][1] + bb[1];
        o0.z = acc[i][2] + bb[2]; o0.w = acc[i][3] + bb[3];
        o1.x = acc[i][4] + bb[4]; o1.y = acc[i][5] + bb[5];
        o1.z = acc[i][6] + bb[6]; o1.w = acc[i][7] + bb[7];
        float* crow = &C[(m0 + ty * 8 + i) * N + n0 + tx * 8];
        *(float4*)&crow[0] = o0;
        *(float4*)&crow[4] = o1;
    }
}

// ============================================================================
// Fused masked-softmax attention (flash style).
// One block per (q-tile of 64 rows, b*h). 256 threads.
// S tile 64x64 via 4x4 micro-tiles; online softmax; O += P@V via 4x4 micro.
// Shared layout (dynamic):
//   Qs[64][68]  (d-major: Qs[d][q]), pre-scaled by 1/8
//   Ks[64][68]  (d-major: Ks[d][k])  -- reused as Ps[64][68] (Ps[k][q])
//   Vs[64][68]  (k-major: Vs[k][d])
//   Ss[64][68]  (Ss[q][k])
//   smM[64], smL[64], smA[64]
// ============================================================================
#define LROW 68
#define ATTN_SMEM_FLOATS (4 * 64 * LROW + 3 * 64)
#define ATTN_SMEM_BYTES  (ATTN_SMEM_FLOATS * 4)

__global__ __launch_bounds__(256) void attn_kernel(const int* __restrict__ mask)
{
    extern __shared__ float sm[];
    float* Qs  = sm;
    float* Ks  = Qs + 64 * LROW;   // also Ps
    float* Vs  = Ks + 64 * LROW;
    float* Ss  = Vs + 64 * LROW;
    float* smM = Ss + 64 * LROW;
    float* smL = smM + 64;
    float* smA = smL + 64;

    const int t  = threadIdx.x;
    const int tx = t & 15;
    const int ty = t >> 4;
    const int q0 = blockIdx.x * 64;
    const int bh = blockIdx.y;
    const int b  = bh >> 4;
    const int h  = bh & 15;
    const int hofs = h * HDIM;

    // Load Q tile (transposed, scaled by 1/8)
#pragma unroll
    for (int p = 0; p < 4; p++) {
        int id   = t + p * 256;        // 0..1023
        int rowl = id >> 4;            // 0..63
        int d4   = id & 15;            // float4 index along D
        float4 qv = *(const float4*)&g_q[(b * TLEN + q0 + rowl) * EDIM + hofs + d4 * 4];
        Qs[(d4 * 4 + 0) * LROW + rowl] = qv.x * 0.125f;
        Qs[(d4 * 4 + 1) * LROW + rowl] = qv.y * 0.125f;
        Qs[(d4 * 4 + 2) * LROW + rowl] = qv.z * 0.125f;
        Qs[(d4 * 4 + 3) * LROW + rowl] = qv.w * 0.125f;
    }
    if (t < 64) { smM[t] = -1e30f; smL[t] = 0.0f; }

    float o[4][4];
#pragma unroll
    for (int i = 0; i < 4; i++)
#pragma unroll
        for (int j = 0; j < 4; j++) o[i][j] = 0.0f;

    __syncthreads();

    for (int kt = 0; kt < TLEN / 64; kt++) {
        // ---- load K tile transposed into Ks[d][k] ----
#pragma unroll
        for (int p = 0; p < 4; p++) {
            int id   = t + p * 256;
            int rowl = id >> 4;
            int d4   = id & 15;
            float4 kv = *(const float4*)&g_k[(b * TLEN + kt * 64 + rowl) * EDIM + hofs + d4 * 4];
            Ks[(d4 * 4 + 0) * LROW + rowl] = kv.x;
            Ks[(d4 * 4 + 1) * LROW + rowl] = kv.y;
            Ks[(d4 * 4 + 2) * LROW + rowl] = kv.z;
            Ks[(d4 * 4 + 3) * LROW + rowl] = kv.w;
        }
        __syncthreads();

        // ---- S = Q*K^T (micro-tiled) ----
        float s[4][4];
#pragma unroll
        for (int i = 0; i < 4; i++)
#pragma unroll
            for (int j = 0; j < 4; j++) s[i][j] = 0.0f;

#pragma unroll 8
        for (int d = 0; d < 64; d++) {
            float4 qa = *(const float4*)&Qs[d * LROW + ty * 4];
            float4 kb = *(const float4*)&Ks[d * LROW + tx * 4];
            float qr[4] = {qa.x, qa.y, qa.z, qa.w};
            float kr[4] = {kb.x, kb.y, kb.z, kb.w};
#pragma unroll
            for (int i = 0; i < 4; i++)
#pragma unroll
                for (int j = 0; j < 4; j++)
                    s[i][j] = fmaf(qr[i], kr[j], s[i][j]);
        }

        // ---- mask + write Ss[q][k] ----
#pragma unroll
        for (int i = 0; i < 4; i++) {
            int qg = q0 + ty * 4 + i;
            int4 mv = *(const int4*)&mask[(b * TLEN + qg) * TLEN + kt * 64 + tx * 4];
            float4 sv;
            sv.x = (mv.x == 0) ? -1.0e9f : s[i][0];
            sv.y = (mv.y == 0) ? -1.0e9f : s[i][1];
            sv.z = (mv.z == 0) ? -1.0e9f : s[i][2];
            sv.w = (mv.w == 0) ? -1.0e9f : s[i][3];
            *(float4*)&Ss[(ty * 4 + i) * LROW + tx * 4] = sv;
        }
        __syncthreads();

        // ---- softmax (threads 0..63, one row each) || V load (threads 64..255)
        if (t < 64) {
            const int r = t;
            float mOld = smM[r];
            float mNew = mOld;
#pragma unroll 8
            for (int j = 0; j < 64; j++)
                mNew = fmaxf(mNew, Ss[r * LROW + j]);
            float alpha = __expf(mOld - mNew);
            float l = smL[r] * alpha;
#pragma unroll 8
            for (int j = 0; j < 64; j++) {
                float p = __expf(Ss[r * LROW + j] - mNew);
                l += p;
                Ks[j * LROW + r] = p;   // Ps[k][q]
            }
            smM[r] = mNew; smL[r] = l; smA[r] = alpha;
        } else {
            for (int id = t - 64; id < 1024; id += 192) {
                int rowl = id >> 4;
                int d4   = id & 15;
                float4 vv = *(const float4*)&g_v[(b * TLEN + kt * 64 + rowl) * EDIM + hofs + d4 * 4];
                *(float4*)&Vs[rowl * LROW + d4 * 4] = vv;
            }
        }
        __syncthreads();

        // ---- O = O*alpha + P@V ----
#pragma unroll
        for (int i = 0; i < 4; i++) {
            float a = smA[ty * 4 + i];
#pragma unroll
            for (int j = 0; j < 4; j++) o[i][j] *= a;
        }
#pragma unroll 8
        for (int kk = 0; kk < 64; kk++) {
            float4 pa = *(const float4*)&Ks[kk * LROW + ty * 4];   // Ps
            float4 vb = *(const float4*)&Vs[kk * LROW + tx * 4];
            float pr[4] = {pa.x, pa.y, pa.z, pa.w};
            float vr[4] = {vb.x, vb.y, vb.z, vb.w};
#pragma unroll
            for (int i = 0; i < 4; i++)
#pragma unroll
                for (int j = 0; j < 4; j++)
                    o[i][j] = fmaf(pr[i], vr[j], o[i][j]);
        }
        __syncthreads();   // protect Ks/Ps/Vs before next tile's loads
    }

    // ---- normalize and write merged-head output ----
#pragma unroll
    for (int i = 0; i < 4; i++) {
        float linv = 1.0f / smL[ty * 4 + i];
        float4 ov;
        ov.x = o[i][0] * linv; ov.y = o[i][1] * linv;
        ov.z = o[i][2] * linv; ov.w = o[i][3] * linv;
        *(float4*)&g_att[(b * TLEN + q0 + ty * 4 + i) * EDIM + hofs + tx * 4] = ov;
    }
}

// ============================================================================
// LayerNorm over E=1024, one block (256 threads) per row; row in registers.
// ============================================================================
__global__ __launch_bounds__(256) void ln_kernel(
    const float* __restrict__ X, const float* __restrict__ gam,
    const float* __restrict__ bet, float* __restrict__ out)
{
    const int row = blockIdx.x;
    const int t   = threadIdx.x;
    __shared__ float red[8];

    float4 x = *(const float4*)&X[row * EDIM + t * 4];
    float s = x.x + x.y + x.z + x.w;
#pragma unroll
    for (int ofs = 16; ofs; ofs >>= 1) s += __shfl_xor_sync(0xffffffffu, s, ofs);
    if ((t & 31) == 0) red[t >> 5] = s;
    __syncthreads();
    float tot = 0.0f;
#pragma unroll
    for (int i = 0; i < 8; i++) tot += red[i];
    float mu = tot * (1.0f / 1024.0f);

    float d0 = x.x - mu, d1 = x.y - mu, d2 = x.z - mu, d3 = x.w - mu;
    float sq = d0 * d0 + d1 * d1 + d2 * d2 + d3 * d3;
    __syncthreads();
#pragma unroll
    for (int ofs = 16; ofs; ofs >>= 1) sq += __shfl_xor_sync(0xffffffffu, sq, ofs);
    if ((t & 31) == 0) red[t >> 5] = sq;
    __syncthreads();
    float vtot = 0.0f;
#pragma unroll
    for (int i = 0; i < 8; i++) vtot += red[i];
    float inv = rsqrtf(vtot * (1.0f / 1024.0f) + 1e-5f);

    float4 g = *(const float4*)&gam[t * 4];
    float4 be = *(const float4*)&bet[t * 4];
    float4 o4;
    o4.x = d0 * inv * g.x + be.x;
    o4.y = d1 * inv * g.y + be.y;
    o4.z = d2 * inv * g.z + be.z;
    o4.w = d3 * inv * g.w + be.w;
    *(float4*)&out[row * EDIM + t * 4] = o4;
}

// ============================================================================
extern "C" void kernel_launch(void* const* d_in, const int* in_sizes, int n_in,
                              void* d_out, int out_size)
{
    const float* query = (const float*)d_in[0];
    const float* key   = (const float*)d_in[1];
    const float* value = (const float*)d_in[2];
    const int*   mask  = (const int*)d_in[3];
    const float* Wq    = (const float*)d_in[4];
    const float* bq    = (const float*)d_in[5];
    const float* Wk    = (const float*)d_in[6];
    const float* bk    = (const float*)d_in[7];
    const float* Wv    = (const float*)d_in[8];
    const float* bv    = (const float*)d_in[9];
    const float* Wo    = (const float*)d_in[10];
    const float* bo    = (const float*)d_in[11];
    const float* gamma = (const float*)d_in[12];
    const float* beta  = (const float*)d_in[13];
    float* out = (float*)d_out;

    float *dq, *dk, *dv, *datt;
    cudaGetSymbolAddress((void**)&dq,   g_q);
    cudaGetSymbolAddress((void**)&dk,   g_k);
    cudaGetSymbolAddress((void**)&dv,   g_v);
    cudaGetSymbolAddress((void**)&datt, g_att);

    cudaFuncSetAttribute(attn_kernel,
                         cudaFuncAttributeMaxDynamicSharedMemorySize,
                         ATTN_SMEM_BYTES);

    dim3 gg(EDIM / 128, MROWS / 128);   // (8, 32)

    // QKV projections
    gemm_nt_bias<<<gg, 256>>>(query, Wq, bq, dq, EDIM, EDIM);
    gemm_nt_bias<<<gg, 256>>>(key,   Wk, bk, dk, EDIM, EDIM);
    gemm_nt_bias<<<gg, 256>>>(value, Wv, bv, dv, EDIM, EDIM);

    // Fused masked-softmax attention
    dim3 ga(TLEN / 64, BATCH * NHEAD);  // (16, 64)
    attn_kernel<<<ga, 256, ATTN_SMEM_BYTES>>>(mask);

    // Output projection (reuse g_q as destination)
    gemm_nt_bias<<<gg, 256>>>(datt, Wo, bo, dq, EDIM, EDIM);

    // LayerNorm -> final output
    ln_kernel<<<MROWS, 256>>>(dq, gamma, beta, out);
}